// round 7
// baseline (speedup 1.0000x reference)
#include <cuda_runtime.h>
#include <cuda_fp16.h>
#include <math.h>
#include <stdint.h>

#define F 128
#define MAXN 50000
#define MAXEGO 1250000
#define MAXE 700000
#define SCAN_TILE 1024
#define MAX_TILES 64

// fp32 scratch
__device__ float g_bufA[MAXN * F];
__device__ float g_bufB[MAXN * F];
// fp16 activation shadows
__device__ __half g_xb[MAXN * F];
__device__ __half g_yb0[MAXN * F];
__device__ __half g_yb1[MAXN * F];
// CSR scratch (list 0 = ego, list 1 = gin edges)
__device__ int g_deg[2 * MAXN];
__device__ int g_off[2 * (MAXN + 1)];
__device__ int g_cur[2 * MAXN];
__device__ int g_adjEgo[MAXEGO];
__device__ int g_adjE[MAXE];
__device__ int g_part[2 * MAX_TILES];

// ---------------------------------------------------------------------------
__global__ void f2h_kernel(const float* __restrict__ x, __half* __restrict__ y, int n4) {
    int i = blockIdx.x * blockDim.x + threadIdx.x;
    if (i >= n4) return;
    float4 v = ((const float4*)x)[i];
    __half2 h0 = __floats2half2_rn(v.x, v.y);
    __half2 h1 = __floats2half2_rn(v.z, v.w);
    uint2 u;
    u.x = *(uint32_t*)&h0; u.y = *(uint32_t*)&h1;
    ((uint2*)y)[i] = u;
}

__global__ void hist2_kernel(const int* __restrict__ w0, int n0,
                             const int* __restrict__ w1, int n1,
                             int* __restrict__ deg0, int* __restrict__ deg1) {
    int i = blockIdx.x * blockDim.x + threadIdx.x;
    if (i < n0) atomicAdd(&deg0[__ldg(w0 + i)], 1);
    if (i < n1) atomicAdd(&deg1[__ldg(w1 + i)], 1);
}

// ---------------------------------------------------------------------------
// 3-phase exclusive scan, two lists via blockIdx.y / thread halves.
__global__ void scan_p1_kernel(const int* __restrict__ deg, int n,
                               int* __restrict__ part, int ntiles) {
    __shared__ int ws[8];
    const int* d = deg + blockIdx.y * n;
    int* p = part + blockIdx.y * ntiles;
    int b = blockIdx.x, t = threadIdx.x;
    int base = b * SCAN_TILE + t * 4;
    int s = 0;
#pragma unroll
    for (int j = 0; j < 4; j++) {
        int i = base + j;
        if (i < n) s += __ldg(d + i);
    }
    int lane = t & 31, wid = t >> 5;
#pragma unroll
    for (int o = 16; o; o >>= 1) s += __shfl_down_sync(0xffffffffu, s, o);
    if (lane == 0) ws[wid] = s;
    __syncthreads();
    if (t < 8) {
        int v = ws[t];
#pragma unroll
        for (int o = 4; o; o >>= 1) v += __shfl_down_sync(0xffu, v, o);
        if (t == 0) p[b] = v;
    }
}

__global__ void scan_p2_kernel(int* __restrict__ part, int nb,
                               int* __restrict__ off, int n, int ntiles) {
    int list = threadIdx.x >> 6;
    int t = threadIdx.x & 63;
    int* pp = part + list * ntiles;
    int* op = off + list * (n + 1);
    int v = (t < nb) ? pp[t] : 0;
    __shared__ int ws[4];
    int lane = t & 31, wid = t >> 5;
    int x = v;
#pragma unroll
    for (int o = 1; o < 32; o <<= 1) {
        int u = __shfl_up_sync(0xffffffffu, x, o);
        if (lane >= o) x += u;
    }
    if (lane == 31) ws[list * 2 + wid] = x;
    __syncthreads();
    int incl = x + (wid ? ws[list * 2] : 0);
    if (t < nb) pp[t] = incl - v;
    if (t == nb - 1) op[n] = incl;
}

__global__ void scan_p3_kernel(const int* __restrict__ deg, int n,
                               const int* __restrict__ part,
                               int* __restrict__ off, int* __restrict__ cur, int ntiles) {
    __shared__ int ws[8];
    const int* d = deg + blockIdx.y * n;
    const int* p = part + blockIdx.y * ntiles;
    int* of = off + blockIdx.y * (n + 1);
    int* cu = cur + blockIdx.y * n;
    int b = blockIdx.x, t = threadIdx.x;
    int base = b * SCAN_TILE + t * 4;
    int v[4];
    int s = 0;
#pragma unroll
    for (int j = 0; j < 4; j++) {
        int i = base + j;
        v[j] = (i < n) ? __ldg(d + i) : 0;
        s += v[j];
    }
    int lane = t & 31, wid = t >> 5;
    int x = s;
#pragma unroll
    for (int o = 1; o < 32; o <<= 1) {
        int u = __shfl_up_sync(0xffffffffu, x, o);
        if (lane >= o) x += u;
    }
    if (lane == 31) ws[wid] = x;
    __syncthreads();
    if (wid == 0) {
        int w = (lane < 8) ? ws[lane] : 0;
#pragma unroll
        for (int o = 1; o < 8; o <<= 1) {
            int u = __shfl_up_sync(0xffffffffu, w, o);
            if (lane >= o) w += u;
        }
        if (lane < 8) ws[lane] = w;
    }
    __syncthreads();
    int run = __ldg(p + b) + (x - s) + (wid ? ws[wid - 1] : 0);
#pragma unroll
    for (int j = 0; j < 4; j++) {
        int i = base + j;
        if (i < n) { of[i] = run; cu[i] = run; }
        run += v[j];
    }
}

__global__ void fill2_kernel(const int* __restrict__ w0, const int* __restrict__ r0, int n0,
                             const int* __restrict__ w1, const int* __restrict__ r1, int n1,
                             int* __restrict__ cur0, int* __restrict__ cur1,
                             int* __restrict__ adj0, int* __restrict__ adj1) {
    int i = blockIdx.x * blockDim.x + threadIdx.x;
    if (i < n0) {
        int pos = atomicAdd(&cur0[__ldg(w0 + i)], 1);
        adj0[pos] = __ldg(r0 + i);
    }
    if (i < n1) {
        int pos = atomicAdd(&cur1[__ldg(w1 + i)], 1);
        adj1[pos] = __ldg(r1 + i);
    }
}

// ---------------------------------------------------------------------------
__device__ __forceinline__ void addh2(float2& a, uint32_t h) {
    float2 f = __half22float2(*(__half2*)&h);
    a.x += f.x; a.y += f.y;
}
__device__ __forceinline__ void mma_f16(float& c0, float& c1, float& c2, float& c3,
                                        uint32_t a0, uint32_t a1, uint32_t a2, uint32_t a3,
                                        uint32_t b0, uint32_t b1) {
    asm volatile(
        "mma.sync.aligned.m16n8k16.row.col.f32.f16.f16.f32 "
        "{%0,%1,%2,%3}, {%4,%5,%6,%7}, {%8,%9}, {%0,%1,%2,%3};"
        : "+f"(c0), "+f"(c1), "+f"(c2), "+f"(c3)
        : "r"(a0), "r"(a1), "r"(a2), "r"(a3), "r"(b0), "r"(b1));
}

// ---------------------------------------------------------------------------
// FUSED segsum + Linear + ReLU, fp16 in/out.
//   GIN=0 (Ego):  A_row[i] = scale * sum_{j in adj[i]} X[j]
//   GIN=1:        A_row[i] = X[i] + sum_{j in adj[i]} X[j]
//   out = relu(A @ W + b), fp16, 64 rows x 128 cols per CTA, warp tile 16x64.
template <bool GIN>
__global__ void __launch_bounds__(256, 3)
fused_seg_gemm_kernel(const __half* __restrict__ X,
                      const int* __restrict__ off, const int* __restrict__ adj,
                      const float* __restrict__ W, const float* __restrict__ bias,
                      __half* __restrict__ Ch, int M, float scale) {
    constexpr int PWH = 136;
    constexpr int PAH = 136;
    extern __shared__ __half sm[];
    __half* Wt = sm;                 // [128][136] halfs: W transposed [n][k]
    __half* As = sm + 128 * PWH;     // [64][136] halfs
    float* bs = (float*)(As + 64 * PAH);  // [128]

    const int tid  = threadIdx.x;
    const int lane = tid & 31;
    const int warp = tid >> 5;
    const int base = blockIdx.x * 64;

    // ---- stage W transposed (coalesced along n) ----
    {
        int tn = tid & 127;
        for (int kb = (tid >> 7) * 8; kb < 128; kb += 16) {
            __half tmp[8];
#pragma unroll
            for (int j = 0; j < 8; j++)
                tmp[j] = __float2half_rn(__ldg(W + (size_t)(kb + j) * 128 + tn));
            *(uint4*)(Wt + tn * PWH + kb) = *(uint4*)tmp;
        }
    }
    if (tid < 128) bs[tid] = __ldg(bias + tid);

    // ---- fused gather stage: warp w handles rows w*8 .. w*8+7 ----
#pragma unroll 1
    for (int i = 0; i < 8; i++) {
        int node = base + warp * 8 + i;
        float2 acc0 = make_float2(0.f, 0.f), acc1 = make_float2(0.f, 0.f);
        if (node < M) {
            if (GIN) {
                uint2 sv = __ldg((const uint2*)(X + (size_t)node * 128) + lane);
                addh2(acc0, sv.x); addh2(acc1, sv.y);
            }
            int s = __ldg(off + node), e = __ldg(off + node + 1);
            for (int j = s; j < e; ) {
                int cnt = min(32, e - j);
                int my = (lane < cnt) ? __ldg(adj + j + lane) : 0;
                int k = 0;
                for (; k + 4 <= cnt; k += 4) {
                    int r0 = __shfl_sync(0xffffffffu, my, k);
                    int r1 = __shfl_sync(0xffffffffu, my, k + 1);
                    int r2 = __shfl_sync(0xffffffffu, my, k + 2);
                    int r3 = __shfl_sync(0xffffffffu, my, k + 3);
                    uint2 u0 = __ldg((const uint2*)(X + (size_t)r0 * 128) + lane);
                    uint2 u1 = __ldg((const uint2*)(X + (size_t)r1 * 128) + lane);
                    uint2 u2 = __ldg((const uint2*)(X + (size_t)r2 * 128) + lane);
                    uint2 u3 = __ldg((const uint2*)(X + (size_t)r3 * 128) + lane);
                    addh2(acc0, u0.x); addh2(acc1, u0.y);
                    addh2(acc0, u1.x); addh2(acc1, u1.y);
                    addh2(acc0, u2.x); addh2(acc1, u2.y);
                    addh2(acc0, u3.x); addh2(acc1, u3.y);
                }
                for (; k < cnt; k++) {
                    int r0 = __shfl_sync(0xffffffffu, my, k);
                    uint2 u0 = __ldg((const uint2*)(X + (size_t)r0 * 128) + lane);
                    addh2(acc0, u0.x); addh2(acc1, u0.y);
                }
                j += cnt;
            }
        }
        __half2 h0 = __floats2half2_rn(acc0.x * scale, acc0.y * scale);
        __half2 h1 = __floats2half2_rn(acc1.x * scale, acc1.y * scale);
        uint2 o;
        o.x = *(uint32_t*)&h0; o.y = *(uint32_t*)&h1;
        *(uint2*)(As + (warp * 8 + i) * PAH + lane * 4) = o;
    }
    __syncthreads();

    // ---- MMA: warp tile 16 rows x 64 cols ----
    const int wr = warp >> 1;   // 0..3
    const int wc = warp & 1;    // 0..1
    const int g  = lane >> 2;   // 0..7
    const int t  = lane & 3;    // 0..3

    float acc[8][4];
#pragma unroll
    for (int nt = 0; nt < 8; nt++)
#pragma unroll
        for (int j = 0; j < 4; j++) acc[nt][j] = 0.f;

    const int r0 = wr * 16 + g;
    const __half* arow0 = As + r0 * PAH;
    const __half* arow1 = As + (r0 + 8) * PAH;
#pragma unroll
    for (int ks = 0; ks < 8; ks++) {
        const int k0 = ks * 16;
        uint32_t a0 = *(const uint32_t*)(arow0 + k0 + 2 * t);
        uint32_t a1 = *(const uint32_t*)(arow1 + k0 + 2 * t);
        uint32_t a2 = *(const uint32_t*)(arow0 + k0 + 2 * t + 8);
        uint32_t a3 = *(const uint32_t*)(arow1 + k0 + 2 * t + 8);
#pragma unroll
        for (int nt = 0; nt < 8; nt++) {
            int n = wc * 64 + nt * 8 + g;
            uint32_t b0 = *(const uint32_t*)(Wt + n * PWH + k0 + 2 * t);
            uint32_t b1 = *(const uint32_t*)(Wt + n * PWH + k0 + 2 * t + 8);
            mma_f16(acc[nt][0], acc[nt][1], acc[nt][2], acc[nt][3],
                    a0, a1, a2, a3, b0, b1);
        }
    }

    // ---- epilogue: bias + relu -> fp16, stride 128 ----
    int gr0 = base + wr * 16 + g;
    int gr1 = gr0 + 8;
#pragma unroll
    for (int nt = 0; nt < 8; nt++) {
        int col = wc * 64 + nt * 8 + t * 2;
        float bx = bs[col], by = bs[col + 1];
        float2 v0 = make_float2(fmaxf(acc[nt][0] + bx, 0.f), fmaxf(acc[nt][1] + by, 0.f));
        float2 v1 = make_float2(fmaxf(acc[nt][2] + bx, 0.f), fmaxf(acc[nt][3] + by, 0.f));
        __half2 h0 = __floats2half2_rn(v0.x, v0.y);
        __half2 h1 = __floats2half2_rn(v1.x, v1.y);
        if (gr0 < M) *(__half2*)(Ch + (size_t)gr0 * 128 + col) = h0;
        if (gr1 < M) *(__half2*)(Ch + (size_t)gr1 * 128 + col) = h1;
    }
}

// ---------------------------------------------------------------------------
// final GEMM: y = Ah @ W[128 x nca] (nca=47, padded to 64), fp32 out stride 64.
__global__ void __launch_bounds__(256, 4)
gemm47_kernel(const __half* __restrict__ Ah, const float* __restrict__ W,
              float* __restrict__ Cf, int M, int nca) {
    constexpr int PWH = 136;
    constexpr int PAH = 136;
    __shared__ __half Wt[64 * PWH];
    __shared__ __half As[64 * PAH];

    const int tid  = threadIdx.x;
    const int lane = tid & 31;
    const int warp = tid >> 5;
    const int base = blockIdx.x * 64;

    {
        int tn = tid & 63;
        for (int kb = (tid >> 6) * 8; kb < 128; kb += 32) {
            __half tmp[8];
#pragma unroll
            for (int j = 0; j < 8; j++) {
                float w = (tn < nca) ? __ldg(W + (size_t)(kb + j) * nca + tn) : 0.f;
                tmp[j] = __float2half_rn(w);
            }
            *(uint4*)(Wt + tn * PWH + kb) = *(uint4*)tmp;
        }
    }
#pragma unroll
    for (int u = tid; u < 64 * 16; u += 256) {
        int rr = u >> 4, c8 = u & 15;
        int row = base + rr;
        uint4 hv = make_uint4(0u, 0u, 0u, 0u);
        if (row < M) hv = __ldg((const uint4*)(Ah + (size_t)row * 128) + c8);
        *(uint4*)(As + rr * PAH + c8 * 8) = hv;
    }
    __syncthreads();

    const int wr = warp >> 1, wc = warp & 1;
    const int g = lane >> 2, t = lane & 3;
    float acc[4][4];
#pragma unroll
    for (int nt = 0; nt < 4; nt++)
#pragma unroll
        for (int j = 0; j < 4; j++) acc[nt][j] = 0.f;

    const int r0 = wr * 16 + g;
    const __half* arow0 = As + r0 * PAH;
    const __half* arow1 = As + (r0 + 8) * PAH;
#pragma unroll
    for (int ks = 0; ks < 8; ks++) {
        const int k0 = ks * 16;
        uint32_t a0 = *(const uint32_t*)(arow0 + k0 + 2 * t);
        uint32_t a1 = *(const uint32_t*)(arow1 + k0 + 2 * t);
        uint32_t a2 = *(const uint32_t*)(arow0 + k0 + 2 * t + 8);
        uint32_t a3 = *(const uint32_t*)(arow1 + k0 + 2 * t + 8);
#pragma unroll
        for (int nt = 0; nt < 4; nt++) {
            int n = wc * 32 + nt * 8 + g;
            uint32_t b0 = *(const uint32_t*)(Wt + n * PWH + k0 + 2 * t);
            uint32_t b1 = *(const uint32_t*)(Wt + n * PWH + k0 + 2 * t + 8);
            mma_f16(acc[nt][0], acc[nt][1], acc[nt][2], acc[nt][3],
                    a0, a1, a2, a3, b0, b1);
        }
    }

    int gr0 = base + wr * 16 + g;
    int gr1 = gr0 + 8;
#pragma unroll
    for (int nt = 0; nt < 4; nt++) {
        int col = wc * 32 + nt * 8 + t * 2;
        if (gr0 < M) *(float2*)(Cf + (size_t)gr0 * 64 + col) = make_float2(acc[nt][0], acc[nt][1]);
        if (gr1 < M) *(float2*)(Cf + (size_t)gr1 * 64 + col) = make_float2(acc[nt][2], acc[nt][3]);
    }
}

// ---------------------------------------------------------------------------
// segsum over CSR, fp32 source rows (64 wide) -> fp32. Warp per node.
__global__ void segsum64f_kernel(const float* __restrict__ x,
                                 const int* __restrict__ off,
                                 const int* __restrict__ adj,
                                 float* __restrict__ out, int n) {
    int gw = (blockIdx.x * blockDim.x + threadIdx.x) >> 5;
    int lane = threadIdx.x & 31;
    if (gw >= n) return;
    int s = __ldg(off + gw), e = __ldg(off + gw + 1);
    float2 acc = make_float2(0.f, 0.f);
    for (int j = s; j < e; ) {
        int cnt = min(32, e - j);
        int my = (lane < cnt) ? __ldg(adj + j + lane) : 0;
        int k = 0;
        for (; k + 2 <= cnt; k += 2) {
            int r0 = __shfl_sync(0xffffffffu, my, k);
            int r1 = __shfl_sync(0xffffffffu, my, k + 1);
            float2 v0 = __ldg((const float2*)(x + (size_t)r0 * 64) + lane);
            float2 v1 = __ldg((const float2*)(x + (size_t)r1 * 64) + lane);
            acc.x += v0.x + v1.x; acc.y += v0.y + v1.y;
        }
        if (k < cnt) {
            int r0 = __shfl_sync(0xffffffffu, my, k);
            float2 v0 = __ldg((const float2*)(x + (size_t)r0 * 64) + lane);
            acc.x += v0.x; acc.y += v0.y;
        }
        j += cnt;
    }
    *(float2*)(out + (size_t)gw * 64 + lane * 2) = acc;
}

// ---------------------------------------------------------------------------
__global__ void final_logsoftmax_kernel(const float* __restrict__ y,
                                        const float* __restrict__ aggr,
                                        const float* __restrict__ bias,
                                        float* __restrict__ out, int M, int nc) {
    int warp = (blockIdx.x * blockDim.x + threadIdx.x) >> 5;
    int lane = threadIdx.x & 31;
    if (warp >= M) return;
    const float* yp = y + (size_t)warp * 64;
    const float* ap = aggr + (size_t)warp * 64;
    int c2 = lane + 32;
    float v1 = (lane < nc) ? yp[lane] + ap[lane] + __ldg(bias + lane) : -INFINITY;
    float v2 = (c2 < nc)   ? yp[c2] + ap[c2] + __ldg(bias + c2)       : -INFINITY;
    float mx = fmaxf(v1, v2);
#pragma unroll
    for (int o = 16; o; o >>= 1) mx = fmaxf(mx, __shfl_xor_sync(0xffffffffu, mx, o));
    float s = ((lane < nc) ? expf(v1 - mx) : 0.f) + ((c2 < nc) ? expf(v2 - mx) : 0.f);
#pragma unroll
    for (int o = 16; o; o >>= 1) s += __shfl_xor_sync(0xffffffffu, s, o);
    float lg = logf(s) + mx;
    float* orow = out + (size_t)warp * nc;
    if (lane < nc) orow[lane] = v1 - lg;
    if (c2 < nc)   orow[c2]   = v2 - lg;
}

// ---------------------------------------------------------------------------
extern "C" void kernel_launch(void* const* d_in, const int* in_sizes, int n_in,
                              void* d_out, int out_size) {
    const float* x_in   = (const float*)d_in[0];
    const int*   ei     = (const int*)d_in[1];
    const int*   ego    = (const int*)d_in[2];
    const float* W_ego0 = (const float*)d_in[3];
    const float* b_ego0 = (const float*)d_in[4];
    const float* W_gin0 = (const float*)d_in[5];
    const float* b_gin0 = (const float*)d_in[6];
    const float* W_ego1 = (const float*)d_in[7];
    const float* b_ego1 = (const float*)d_in[8];
    const float* W_gin1 = (const float*)d_in[9];
    const float* b_gin1 = (const float*)d_in[10];

    int N    = in_sizes[0] / F;
    int E    = in_sizes[1] / 2;
    int EGO  = in_sizes[2] / 2;
    int OUTC = in_sizes[10];
    float invN = 1.0f / (float)N;

    float *bufA, *bufB;
    __half *xb, *yb0, *yb1;
    int *deg, *off, *cur, *adjEgo, *adjE, *part;
    cudaGetSymbolAddress((void**)&bufA, g_bufA);
    cudaGetSymbolAddress((void**)&bufB, g_bufB);
    cudaGetSymbolAddress((void**)&xb, g_xb);
    cudaGetSymbolAddress((void**)&yb0, g_yb0);
    cudaGetSymbolAddress((void**)&yb1, g_yb1);
    cudaGetSymbolAddress((void**)&deg, g_deg);
    cudaGetSymbolAddress((void**)&off, g_off);
    cudaGetSymbolAddress((void**)&cur, g_cur);
    cudaGetSymbolAddress((void**)&adjEgo, g_adjEgo);
    cudaGetSymbolAddress((void**)&adjE, g_adjE);
    cudaGetSymbolAddress((void**)&part, g_part);

    int *degEgo = deg, *degE = deg + N;
    int *offEgo = off, *offE = off + (N + 1);
    int *curEgo = cur, *curE = cur + N;

    const size_t smf = (size_t)(128 * 136 + 64 * 136) * 2 + 128 * 4;  // 52736
    cudaFuncSetAttribute(fused_seg_gemm_kernel<false>,
                         cudaFuncAttributeMaxDynamicSharedMemorySize, (int)smf);
    cudaFuncSetAttribute(fused_seg_gemm_kernel<true>,
                         cudaFuncAttributeMaxDynamicSharedMemorySize, (int)smf);

    int gf = (N + 63) / 64;
    int sg = (N * 32 + 255) / 256;
    int ntiles = (N + SCAN_TILE - 1) / SCAN_TILE;
    int maxE = (EGO > E) ? EGO : E;
    dim3 scang(ntiles, 2);

    // ---- CSR build + fp16 convert ----
    cudaMemsetAsync(deg, 0, 2 * N * sizeof(int), 0);
    f2h_kernel<<<(N * F / 4 + 255) / 256, 256>>>(x_in, xb, N * F / 4);
    hist2_kernel<<<(maxE + 255) / 256, 256>>>(ego, EGO, ei + E, E, degEgo, degE);
    scan_p1_kernel<<<scang, 256>>>(deg, N, part, ntiles);
    scan_p2_kernel<<<1, 128>>>(part, ntiles, off, N, ntiles);
    scan_p3_kernel<<<scang, 256>>>(deg, N, part, off, cur, ntiles);
    fill2_kernel<<<(maxE + 255) / 256, 256>>>(ego, ego + EGO, EGO, ei + E, ei, E,
                                              curEgo, curE, adjEgo, adjE);

    // ---- layer 0: Ego (fused) ----
    fused_seg_gemm_kernel<false><<<gf, 256, smf>>>(
        xb, offEgo, adjEgo, W_ego0, b_ego0, yb0, N, invN);
    // ---- layer 0: GIN (fused) ----
    fused_seg_gemm_kernel<true><<<gf, 256, smf>>>(
        yb0, offE, adjE, W_gin0, b_gin0, yb1, N, 1.0f);
    // ---- layer 1: Ego (fused) ----
    fused_seg_gemm_kernel<false><<<gf, 256, smf>>>(
        yb1, offEgo, adjEgo, W_ego1, b_ego1, yb0, N, invN);
    // ---- layer 1: GIN via linearity ----
    gemm47_kernel<<<gf, 256>>>(yb0, W_gin1, bufB, N, OUTC);
    segsum64f_kernel<<<sg, 256>>>(bufB, offE, adjE, bufA, N);
    final_logsoftmax_kernel<<<sg, 256>>>(bufB, bufA, b_gin1, (float*)d_out, N, OUTC);
}

// round 8
// speedup vs baseline: 1.1819x; 1.1819x over previous
#include <cuda_runtime.h>
#include <cuda_fp16.h>
#include <math.h>
#include <stdint.h>

#define F 128
#define MAXN 50000
#define MAXEGO 1250000
#define MAXE 700000
#define SCAN_TILE 1024
#define MAX_TILES 64

// fp32 scratch
__device__ float g_bufA[MAXN * F];
__device__ float g_bufB[MAXN * F];
// fp16 activation shadows
__device__ __half g_xb[MAXN * F];
__device__ __half g_yb0[MAXN * F];
__device__ __half g_yb1[MAXN * F];
__device__ __half g_ah[MAXN * F];   // fp16 aggregation output
// CSR scratch (list 0 = ego, list 1 = gin edges)
__device__ int g_deg[2 * MAXN];
__device__ int g_off[2 * (MAXN + 1)];
__device__ int g_cur[2 * MAXN];
__device__ int g_adjEgo[MAXEGO];
__device__ int g_adjE[MAXE];
__device__ int g_part[2 * MAX_TILES];

// ---------------------------------------------------------------------------
__global__ void f2h_kernel(const float* __restrict__ x, __half* __restrict__ y, int n4) {
    int i = blockIdx.x * blockDim.x + threadIdx.x;
    if (i >= n4) return;
    float4 v = ((const float4*)x)[i];
    __half2 h0 = __floats2half2_rn(v.x, v.y);
    __half2 h1 = __floats2half2_rn(v.z, v.w);
    uint2 u;
    u.x = *(uint32_t*)&h0; u.y = *(uint32_t*)&h1;
    ((uint2*)y)[i] = u;
}

__global__ void hist2_kernel(const int* __restrict__ w0, int n0,
                             const int* __restrict__ w1, int n1,
                             int* __restrict__ deg0, int* __restrict__ deg1) {
    int i = blockIdx.x * blockDim.x + threadIdx.x;
    if (i < n0) atomicAdd(&deg0[__ldg(w0 + i)], 1);
    if (i < n1) atomicAdd(&deg1[__ldg(w1 + i)], 1);
}

// ---------------------------------------------------------------------------
// 2-phase exclusive scan, two lists via blockIdx.y.
__global__ void scan_p1_kernel(const int* __restrict__ deg, int n,
                               int* __restrict__ part, int ntiles) {
    __shared__ int ws[8];
    const int* d = deg + blockIdx.y * n;
    int* p = part + blockIdx.y * ntiles;
    int b = blockIdx.x, t = threadIdx.x;
    int base = b * SCAN_TILE + t * 4;
    int s = 0;
#pragma unroll
    for (int j = 0; j < 4; j++) {
        int i = base + j;
        if (i < n) s += __ldg(d + i);
    }
    int lane = t & 31, wid = t >> 5;
#pragma unroll
    for (int o = 16; o; o >>= 1) s += __shfl_down_sync(0xffffffffu, s, o);
    if (lane == 0) ws[wid] = s;
    __syncthreads();
    if (t < 8) {
        int v = ws[t];
#pragma unroll
        for (int o = 4; o; o >>= 1) v += __shfl_down_sync(0xffu, v, o);
        if (t == 0) p[b] = v;
    }
}

// p3 with in-block scan of partials (p2 fused). nb = #tiles (<=64).
__global__ void scan_p3_kernel(const int* __restrict__ deg, int n,
                               const int* __restrict__ part,
                               int* __restrict__ off, int* __restrict__ cur,
                               int ntiles, int nb) {
    __shared__ int ws[8];
    __shared__ int wtot[2];
    __shared__ int psc[MAX_TILES + 1];
    const int list = blockIdx.y;
    const int* d = deg + list * n;
    int* of = off + list * (n + 1);
    int* cu = cur + list * n;
    int b = blockIdx.x, t = threadIdx.x;

    // in-block exclusive scan of partials (64 threads, 2 warps)
    int px = 0;
    if (t < 64) {
        int pv = (t < nb) ? __ldg(part + list * ntiles + t) : 0;
        int lane = t & 31, w = t >> 5;
        px = pv;
#pragma unroll
        for (int o = 1; o < 32; o <<= 1) {
            int u = __shfl_up_sync(0xffffffffu, px, o);
            if (lane >= o) px += u;
        }
        if (lane == 31) wtot[w] = px;
    }
    __syncthreads();
    if (t < 64) {
        int incl = px + ((t >> 5) ? wtot[0] : 0);
        psc[t + 1] = incl;
        if (t == 0) psc[0] = 0;
    }
    __syncthreads();
    if (b == 0 && t == 0) of[n] = psc[nb];
    const int tilebase = psc[b];

    // per-tile scan of deg
    int base = b * SCAN_TILE + t * 4;
    int v[4];
    int s = 0;
#pragma unroll
    for (int j = 0; j < 4; j++) {
        int i = base + j;
        v[j] = (i < n) ? __ldg(d + i) : 0;
        s += v[j];
    }
    int lane = t & 31, wid = t >> 5;
    int x = s;
#pragma unroll
    for (int o = 1; o < 32; o <<= 1) {
        int u = __shfl_up_sync(0xffffffffu, x, o);
        if (lane >= o) x += u;
    }
    if (lane == 31) ws[wid] = x;
    __syncthreads();
    if (wid == 0) {
        int w = (lane < 8) ? ws[lane] : 0;
#pragma unroll
        for (int o = 1; o < 8; o <<= 1) {
            int u = __shfl_up_sync(0xffffffffu, w, o);
            if (lane >= o) w += u;
        }
        if (lane < 8) ws[lane] = w;
    }
    __syncthreads();
    int run = tilebase + (x - s) + (wid ? ws[wid - 1] : 0);
#pragma unroll
    for (int j = 0; j < 4; j++) {
        int i = base + j;
        if (i < n) { of[i] = run; cu[i] = run; }
        run += v[j];
    }
}

__global__ void fill2_kernel(const int* __restrict__ w0, const int* __restrict__ r0, int n0,
                             const int* __restrict__ w1, const int* __restrict__ r1, int n1,
                             int* __restrict__ cur0, int* __restrict__ cur1,
                             int* __restrict__ adj0, int* __restrict__ adj1) {
    int i = blockIdx.x * blockDim.x + threadIdx.x;
    if (i < n0) {
        int pos = atomicAdd(&cur0[__ldg(w0 + i)], 1);
        adj0[pos] = __ldg(r0 + i);
    }
    if (i < n1) {
        int pos = atomicAdd(&cur1[__ldg(w1 + i)], 1);
        adj1[pos] = __ldg(r1 + i);
    }
}

// ---------------------------------------------------------------------------
__device__ __forceinline__ void addh2(float2& a, uint32_t h) {
    float2 f = __half22float2(*(__half2*)&h);
    a.x += f.x; a.y += f.y;
}

// segsum over CSR, fp16 rows (128 halfs) -> fp16 out (fp32 accum).
// SELF: add X[node] (GIN). scale applied before store (Ego 1/N).
template <bool SELF>
__global__ void segsum128h_kernel(const __half* __restrict__ x,
                                  const int* __restrict__ off,
                                  const int* __restrict__ adj,
                                  __half* __restrict__ out, int n, float scale) {
    int gw = (blockIdx.x * blockDim.x + threadIdx.x) >> 5;
    int lane = threadIdx.x & 31;
    if (gw >= n) return;
    int s = __ldg(off + gw), e = __ldg(off + gw + 1);
    float2 acc0 = make_float2(0.f, 0.f), acc1 = make_float2(0.f, 0.f);
    if (SELF) {
        uint2 sv = __ldg((const uint2*)(x + (size_t)gw * 128) + lane);
        addh2(acc0, sv.x); addh2(acc1, sv.y);
    }
    for (int j = s; j < e; ) {
        int cnt = min(32, e - j);
        int my = (lane < cnt) ? __ldg(adj + j + lane) : 0;
        int k = 0;
        for (; k + 4 <= cnt; k += 4) {
            int r0 = __shfl_sync(0xffffffffu, my, k);
            int r1 = __shfl_sync(0xffffffffu, my, k + 1);
            int r2 = __shfl_sync(0xffffffffu, my, k + 2);
            int r3 = __shfl_sync(0xffffffffu, my, k + 3);
            uint2 u0 = __ldg((const uint2*)(x + (size_t)r0 * 128) + lane);
            uint2 u1 = __ldg((const uint2*)(x + (size_t)r1 * 128) + lane);
            uint2 u2 = __ldg((const uint2*)(x + (size_t)r2 * 128) + lane);
            uint2 u3 = __ldg((const uint2*)(x + (size_t)r3 * 128) + lane);
            addh2(acc0, u0.x); addh2(acc1, u0.y);
            addh2(acc0, u1.x); addh2(acc1, u1.y);
            addh2(acc0, u2.x); addh2(acc1, u2.y);
            addh2(acc0, u3.x); addh2(acc1, u3.y);
        }
        for (; k < cnt; k++) {
            int r0 = __shfl_sync(0xffffffffu, my, k);
            uint2 u0 = __ldg((const uint2*)(x + (size_t)r0 * 128) + lane);
            addh2(acc0, u0.x); addh2(acc1, u0.y);
        }
        j += cnt;
    }
    __half2 h0 = __floats2half2_rn(acc0.x * scale, acc0.y * scale);
    __half2 h1 = __floats2half2_rn(acc1.x * scale, acc1.y * scale);
    uint2 o;
    o.x = *(uint32_t*)&h0; o.y = *(uint32_t*)&h1;
    *(uint2*)(out + (size_t)gw * 128 + lane * 4) = o;
}

// segsum over CSR, fp32 source rows (64 wide) -> fp32. Warp per node.
__global__ void segsum64f_kernel(const float* __restrict__ x,
                                 const int* __restrict__ off,
                                 const int* __restrict__ adj,
                                 float* __restrict__ out, int n) {
    int gw = (blockIdx.x * blockDim.x + threadIdx.x) >> 5;
    int lane = threadIdx.x & 31;
    if (gw >= n) return;
    int s = __ldg(off + gw), e = __ldg(off + gw + 1);
    float2 acc = make_float2(0.f, 0.f);
    for (int j = s; j < e; ) {
        int cnt = min(32, e - j);
        int my = (lane < cnt) ? __ldg(adj + j + lane) : 0;
        int k = 0;
        for (; k + 2 <= cnt; k += 2) {
            int r0 = __shfl_sync(0xffffffffu, my, k);
            int r1 = __shfl_sync(0xffffffffu, my, k + 1);
            float2 v0 = __ldg((const float2*)(x + (size_t)r0 * 64) + lane);
            float2 v1 = __ldg((const float2*)(x + (size_t)r1 * 64) + lane);
            acc.x += v0.x + v1.x; acc.y += v0.y + v1.y;
        }
        if (k < cnt) {
            int r0 = __shfl_sync(0xffffffffu, my, k);
            float2 v0 = __ldg((const float2*)(x + (size_t)r0 * 64) + lane);
            acc.x += v0.x; acc.y += v0.y;
        }
        j += cnt;
    }
    *(float2*)(out + (size_t)gw * 64 + lane * 2) = acc;
}

// ---------------------------------------------------------------------------
__device__ __forceinline__ void mma_f16(float& c0, float& c1, float& c2, float& c3,
                                        uint32_t a0, uint32_t a1, uint32_t a2, uint32_t a3,
                                        uint32_t b0, uint32_t b1) {
    asm volatile(
        "mma.sync.aligned.m16n8k16.row.col.f32.f16.f16.f32 "
        "{%0,%1,%2,%3}, {%4,%5,%6,%7}, {%8,%9}, {%0,%1,%2,%3};"
        : "+f"(c0), "+f"(c1), "+f"(c2), "+f"(c3)
        : "r"(a0), "r"(a1), "r"(a2), "r"(a3), "r"(b0), "r"(b1));
}

// fp16 GEMM: C = relu(Ah @ W + b), 64x64 tile per CTA, grid.y = col tile of 64.
// Ah fp16 rows stride 128; out fp16 rows stride 128.
__global__ void __launch_bounds__(256, 4)
gemm_h_kernel(const __half* __restrict__ Ah,
              const float* __restrict__ W, const float* __restrict__ bias,
              __half* __restrict__ Ch, int M) {
    constexpr int PWH = 136;
    constexpr int PAH = 136;
    __shared__ __half Wt[64 * PWH];
    __shared__ __half As[64 * PAH];
    __shared__ float bs[64];

    const int tid  = threadIdx.x;
    const int lane = tid & 31;
    const int warp = tid >> 5;
    const int cb   = blockIdx.y * 64;
    const int base = blockIdx.x * 64;

    {
        int tn = tid & 63;
        int gc = cb + tn;
        for (int kb = (tid >> 6) * 8; kb < 128; kb += 32) {
            __half tmp[8];
#pragma unroll
            for (int j = 0; j < 8; j++)
                tmp[j] = __float2half_rn(__ldg(W + (size_t)(kb + j) * 128 + gc));
            *(uint4*)(Wt + tn * PWH + kb) = *(uint4*)tmp;
        }
    }
    if (tid < 64) bs[tid] = __ldg(bias + cb + tid);

#pragma unroll
    for (int u = tid; u < 64 * 16; u += 256) {
        int rr = u >> 4, c8 = u & 15;
        int row = base + rr;
        uint4 hv = make_uint4(0u, 0u, 0u, 0u);
        if (row < M) hv = __ldg((const uint4*)(Ah + (size_t)row * 128) + c8);
        *(uint4*)(As + rr * PAH + c8 * 8) = hv;
    }
    __syncthreads();

    const int wr = warp >> 1, wc = warp & 1;
    const int g = lane >> 2, t = lane & 3;
    float acc[4][4];
#pragma unroll
    for (int nt = 0; nt < 4; nt++)
#pragma unroll
        for (int j = 0; j < 4; j++) acc[nt][j] = 0.f;

    const int r0 = wr * 16 + g;
    const __half* arow0 = As + r0 * PAH;
    const __half* arow1 = As + (r0 + 8) * PAH;
#pragma unroll
    for (int ks = 0; ks < 8; ks++) {
        const int k0 = ks * 16;
        uint32_t a0 = *(const uint32_t*)(arow0 + k0 + 2 * t);
        uint32_t a1 = *(const uint32_t*)(arow1 + k0 + 2 * t);
        uint32_t a2 = *(const uint32_t*)(arow0 + k0 + 2 * t + 8);
        uint32_t a3 = *(const uint32_t*)(arow1 + k0 + 2 * t + 8);
#pragma unroll
        for (int nt = 0; nt < 4; nt++) {
            int n = wc * 32 + nt * 8 + g;
            uint32_t b0 = *(const uint32_t*)(Wt + n * PWH + k0 + 2 * t);
            uint32_t b1 = *(const uint32_t*)(Wt + n * PWH + k0 + 2 * t + 8);
            mma_f16(acc[nt][0], acc[nt][1], acc[nt][2], acc[nt][3],
                    a0, a1, a2, a3, b0, b1);
        }
    }

    int gr0 = base + wr * 16 + g;
    int gr1 = gr0 + 8;
#pragma unroll
    for (int nt = 0; nt < 4; nt++) {
        int col = wc * 32 + nt * 8 + t * 2;
        float bx = bs[col], by = bs[col + 1];
        __half2 h0 = __floats2half2_rn(fmaxf(acc[nt][0] + bx, 0.f), fmaxf(acc[nt][1] + by, 0.f));
        __half2 h1 = __floats2half2_rn(fmaxf(acc[nt][2] + bx, 0.f), fmaxf(acc[nt][3] + by, 0.f));
        int gcol = cb + col;
        if (gr0 < M) *(__half2*)(Ch + (size_t)gr0 * 128 + gcol) = h0;
        if (gr1 < M) *(__half2*)(Ch + (size_t)gr1 * 128 + gcol) = h1;
    }
}

// final GEMM: y = Ah @ W[128 x nca] (nca=47, padded 64), fp32 out stride 64.
__global__ void __launch_bounds__(256, 4)
gemm47_kernel(const __half* __restrict__ Ah, const float* __restrict__ W,
              float* __restrict__ Cf, int M, int nca) {
    constexpr int PWH = 136;
    constexpr int PAH = 136;
    __shared__ __half Wt[64 * PWH];
    __shared__ __half As[64 * PAH];

    const int tid  = threadIdx.x;
    const int lane = tid & 31;
    const int warp = tid >> 5;
    const int base = blockIdx.x * 64;

    {
        int tn = tid & 63;
        for (int kb = (tid >> 6) * 8; kb < 128; kb += 32) {
            __half tmp[8];
#pragma unroll
            for (int j = 0; j < 8; j++) {
                float w = (tn < nca) ? __ldg(W + (size_t)(kb + j) * nca + tn) : 0.f;
                tmp[j] = __float2half_rn(w);
            }
            *(uint4*)(Wt + tn * PWH + kb) = *(uint4*)tmp;
        }
    }
#pragma unroll
    for (int u = tid; u < 64 * 16; u += 256) {
        int rr = u >> 4, c8 = u & 15;
        int row = base + rr;
        uint4 hv = make_uint4(0u, 0u, 0u, 0u);
        if (row < M) hv = __ldg((const uint4*)(Ah + (size_t)row * 128) + c8);
        *(uint4*)(As + rr * PAH + c8 * 8) = hv;
    }
    __syncthreads();

    const int wr = warp >> 1, wc = warp & 1;
    const int g = lane >> 2, t = lane & 3;
    float acc[4][4];
#pragma unroll
    for (int nt = 0; nt < 4; nt++)
#pragma unroll
        for (int j = 0; j < 4; j++) acc[nt][j] = 0.f;

    const int r0 = wr * 16 + g;
    const __half* arow0 = As + r0 * PAH;
    const __half* arow1 = As + (r0 + 8) * PAH;
#pragma unroll
    for (int ks = 0; ks < 8; ks++) {
        const int k0 = ks * 16;
        uint32_t a0 = *(const uint32_t*)(arow0 + k0 + 2 * t);
        uint32_t a1 = *(const uint32_t*)(arow1 + k0 + 2 * t);
        uint32_t a2 = *(const uint32_t*)(arow0 + k0 + 2 * t + 8);
        uint32_t a3 = *(const uint32_t*)(arow1 + k0 + 2 * t + 8);
#pragma unroll
        for (int nt = 0; nt < 4; nt++) {
            int n = wc * 32 + nt * 8 + g;
            uint32_t b0 = *(const uint32_t*)(Wt + n * PWH + k0 + 2 * t);
            uint32_t b1 = *(const uint32_t*)(Wt + n * PWH + k0 + 2 * t + 8);
            mma_f16(acc[nt][0], acc[nt][1], acc[nt][2], acc[nt][3],
                    a0, a1, a2, a3, b0, b1);
        }
    }

    int gr0 = base + wr * 16 + g;
    int gr1 = gr0 + 8;
#pragma unroll
    for (int nt = 0; nt < 4; nt++) {
        int col = wc * 32 + nt * 8 + t * 2;
        if (gr0 < M) *(float2*)(Cf + (size_t)gr0 * 64 + col) = make_float2(acc[nt][0], acc[nt][1]);
        if (gr1 < M) *(float2*)(Cf + (size_t)gr1 * 64 + col) = make_float2(acc[nt][2], acc[nt][3]);
    }
}

// ---------------------------------------------------------------------------
__global__ void final_logsoftmax_kernel(const float* __restrict__ y,
                                        const float* __restrict__ aggr,
                                        const float* __restrict__ bias,
                                        float* __restrict__ out, int M, int nc) {
    int warp = (blockIdx.x * blockDim.x + threadIdx.x) >> 5;
    int lane = threadIdx.x & 31;
    if (warp >= M) return;
    const float* yp = y + (size_t)warp * 64;
    const float* ap = aggr + (size_t)warp * 64;
    int c2 = lane + 32;
    float v1 = (lane < nc) ? yp[lane] + ap[lane] + __ldg(bias + lane) : -INFINITY;
    float v2 = (c2 < nc)   ? yp[c2] + ap[c2] + __ldg(bias + c2)       : -INFINITY;
    float mx = fmaxf(v1, v2);
#pragma unroll
    for (int o = 16; o; o >>= 1) mx = fmaxf(mx, __shfl_xor_sync(0xffffffffu, mx, o));
    float s = ((lane < nc) ? expf(v1 - mx) : 0.f) + ((c2 < nc) ? expf(v2 - mx) : 0.f);
#pragma unroll
    for (int o = 16; o; o >>= 1) s += __shfl_xor_sync(0xffffffffu, s, o);
    float lg = logf(s) + mx;
    float* orow = out + (size_t)warp * nc;
    if (lane < nc) orow[lane] = v1 - lg;
    if (c2 < nc)   orow[c2]   = v2 - lg;
}

// ---------------------------------------------------------------------------
extern "C" void kernel_launch(void* const* d_in, const int* in_sizes, int n_in,
                              void* d_out, int out_size) {
    const float* x_in   = (const float*)d_in[0];
    const int*   ei     = (const int*)d_in[1];
    const int*   ego    = (const int*)d_in[2];
    const float* W_ego0 = (const float*)d_in[3];
    const float* b_ego0 = (const float*)d_in[4];
    const float* W_gin0 = (const float*)d_in[5];
    const float* b_gin0 = (const float*)d_in[6];
    const float* W_ego1 = (const float*)d_in[7];
    const float* b_ego1 = (const float*)d_in[8];
    const float* W_gin1 = (const float*)d_in[9];
    const float* b_gin1 = (const float*)d_in[10];

    int N    = in_sizes[0] / F;
    int E    = in_sizes[1] / 2;
    int EGO  = in_sizes[2] / 2;
    int OUTC = in_sizes[10];
    float invN = 1.0f / (float)N;

    float *bufA, *bufB;
    __half *xb, *yb0, *yb1, *ah;
    int *deg, *off, *cur, *adjEgo, *adjE, *part;
    cudaGetSymbolAddress((void**)&bufA, g_bufA);
    cudaGetSymbolAddress((void**)&bufB, g_bufB);
    cudaGetSymbolAddress((void**)&xb, g_xb);
    cudaGetSymbolAddress((void**)&yb0, g_yb0);
    cudaGetSymbolAddress((void**)&yb1, g_yb1);
    cudaGetSymbolAddress((void**)&ah, g_ah);
    cudaGetSymbolAddress((void**)&deg, g_deg);
    cudaGetSymbolAddress((void**)&off, g_off);
    cudaGetSymbolAddress((void**)&cur, g_cur);
    cudaGetSymbolAddress((void**)&adjEgo, g_adjEgo);
    cudaGetSymbolAddress((void**)&adjE, g_adjE);
    cudaGetSymbolAddress((void**)&part, g_part);

    int *degEgo = deg, *degE = deg + N;
    int *offEgo = off, *offE = off + (N + 1);
    int *curEgo = cur, *curE = cur + N;

    dim3 g128((N + 63) / 64, 2);
    int gf = (N + 63) / 64;
    int sg = (N * 32 + 255) / 256;
    int ntiles = (N + SCAN_TILE - 1) / SCAN_TILE;
    int maxE = (EGO > E) ? EGO : E;
    dim3 scang(ntiles, 2);

    // ---- CSR build + fp16 convert ----
    cudaMemsetAsync(deg, 0, 2 * N * sizeof(int), 0);
    f2h_kernel<<<(N * F / 4 + 255) / 256, 256>>>(x_in, xb, N * F / 4);
    hist2_kernel<<<(maxE + 255) / 256, 256>>>(ego, EGO, ei + E, E, degEgo, degE);
    scan_p1_kernel<<<scang, 256>>>(deg, N, part, ntiles);
    scan_p3_kernel<<<scang, 256>>>(deg, N, part, off, cur, ntiles, ntiles);
    fill2_kernel<<<(maxE + 255) / 256, 256>>>(ego, ego + EGO, EGO, ei + E, ei, E,
                                              curEgo, curE, adjEgo, adjE);

    // ---- layer 0: Ego ----
    segsum128h_kernel<false><<<sg, 256>>>(xb, offEgo, adjEgo, ah, N, invN);
    gemm_h_kernel<<<g128, 256>>>(ah, W_ego0, b_ego0, yb0, N);
    // ---- layer 0: GIN (self-add folded into segsum) ----
    segsum128h_kernel<true><<<sg, 256>>>(yb0, offE, adjE, ah, N, 1.0f);
    gemm_h_kernel<<<g128, 256>>>(ah, W_gin0, b_gin0, yb1, N);
    // ---- layer 1: Ego ----
    segsum128h_kernel<false><<<sg, 256>>>(yb1, offEgo, adjEgo, ah, N, invN);
    gemm_h_kernel<<<g128, 256>>>(ah, W_ego1, b_ego1, yb0, N);
    // ---- layer 1: GIN via linearity ----
    gemm47_kernel<<<gf, 256>>>(yb0, W_gin1, bufB, N, OUTC);
    segsum64f_kernel<<<sg, 256>>>(bufB, offE, adjE, bufA, N);
    final_logsoftmax_kernel<<<sg, 256>>>(bufB, bufA, b_gin1, (float*)d_out, N, OUTC);
}